// round 14
// baseline (speedup 1.0000x reference)
#include <cuda_runtime.h>
#include <math.h>

#define BB 64
#define NN 8192
#define WW 64
#define HH 4
#define CTRL 792   // H*(3W+6)
#define K1TILES 64 // NN / K1_ROWSPB
#define K2SPLIT 8  // tiles per (b,h) in k2

// ---------------- scratch (no allocation allowed) ----------------
__device__ float g_scores[(size_t)BB*HH*NN];       // beta * cosine
__device__ float g_w     [(size_t)BB*HH*NN];       // UNNORMALIZED sharpened weights
__device__ float g_pmax [BB*HH*K1TILES];           // per-tile score max
__device__ float g_psum [BB*HH*K1TILES];           // per-tile sum exp(s - pmax)
__device__ float g_tpart[BB*HH*K2SPLIT];           // per-tile sharpen partial sums

__device__ __forceinline__ float softplusf(float x){
    return x > 20.f ? x : log1pf(expf(x));
}
__device__ __forceinline__ float sigmoidf(float x){
    return 1.f/(1.f + expf(-x));
}

// ---------------- k1: scores + per-tile softmax partials ----------------
// Controls (tanh keys, norms, beta) computed in-block from ctrl (L2-resident).
#define K1T 128
#define K1_ROWSPB 128
#define TP 17                     // row pitch in float4
__global__ __launch_bounds__(K1T) void k1_scores(const float* __restrict__ mem,
                                                 const float* __restrict__ ctrl){
    int b  = blockIdx.y;
    int n0 = blockIdx.x * K1_ROWSPB;
    __shared__ float4 tile[K1_ROWSPB * TP];
    __shared__ float skey[HH*WW];
    __shared__ float sb[HH], skn[HH];
    __shared__ float rmax[4][HH], rsum[4][HH], bmax[HH];
    int t = threadIdx.x;
    int wid = t >> 5, lane = t & 31;
    const float* c = ctrl + b*CTRL;

    // stream the memory tile into padded SMEM (coalesced; covers control math)
    const float4* gsrc = (const float4*)mem + ((size_t)b*NN + n0)*(WW/4);
    #pragma unroll
    for (int i = 0; i < 16; i++){
        int g = t + K1T*i;
        tile[(g >> 4)*TP + (g & 15)] = gsrc[g];
    }

    // in-block control transforms
    skey[t]       = tanhf(c[t]);        // keys occupy ctrl[0..255] h-major
    skey[t + 128] = tanhf(c[t + 128]);
    __syncthreads();
    {   // warp wid -> head wid: key norm + beta
        float k0 = skey[wid*WW + lane], k1 = skey[wid*WW + 32 + lane];
        float sqk = k0*k0 + k1*k1;
        #pragma unroll
        for (int o = 16; o; o >>= 1) sqk += __shfl_xor_sync(0xffffffffu, sqk, o);
        if (lane == 0){
            skn[wid] = sqrtf(sqk);
            sb[wid]  = softplusf(c[768 + wid]);
        }
    }
    __syncthreads();

    const float4* mrow = tile + t*TP;
    const float4* kk   = (const float4*)skey;
    float d0 = 0.f, d1 = 0.f, d2 = 0.f, d3 = 0.f, sq = 0.f;
    #pragma unroll
    for (int j = 0; j < 16; j++){
        float4 m  = mrow[j];
        float4 c0 = kk[0*16 + j];
        float4 c1 = kk[1*16 + j];
        float4 c2 = kk[2*16 + j];
        float4 c3 = kk[3*16 + j];
        sq += m.x*m.x + m.y*m.y + m.z*m.z + m.w*m.w;
        d0 += m.x*c0.x + m.y*c0.y + m.z*c0.z + m.w*c0.w;
        d1 += m.x*c1.x + m.y*c1.y + m.z*c1.z + m.w*c1.w;
        d2 += m.x*c2.x + m.y*c2.y + m.z*c2.z + m.w*c2.w;
        d3 += m.x*c3.x + m.y*c3.y + m.z*c3.z + m.w*c3.w;
    }
    float mn  = sqrtf(sq);
    float s[HH];
    s[0] = sb[0]*d0/(skn[0]*mn + 1e-8f);
    s[1] = sb[1]*d1/(skn[1]*mn + 1e-8f);
    s[2] = sb[2]*d2/(skn[2]*mn + 1e-8f);
    s[3] = sb[3]*d3/(skn[3]*mn + 1e-8f);
    size_t base = (size_t)b*HH*NN + n0 + t;
    #pragma unroll
    for (int h = 0; h < HH; h++) g_scores[base + (size_t)h*NN] = s[h];

    #pragma unroll
    for (int h = 0; h < HH; h++){
        float v = s[h];
        #pragma unroll
        for (int o = 16; o; o >>= 1) v = fmaxf(v, __shfl_xor_sync(0xffffffffu, v, o));
        if (lane == 0) rmax[wid][h] = v;
    }
    __syncthreads();
    if (t < HH)
        bmax[t] = fmaxf(fmaxf(rmax[0][t], rmax[1][t]), fmaxf(rmax[2][t], rmax[3][t]));
    __syncthreads();
    #pragma unroll
    for (int h = 0; h < HH; h++){
        float v = __expf(s[h] - bmax[h]);
        #pragma unroll
        for (int o = 16; o; o >>= 1) v += __shfl_xor_sync(0xffffffffu, v, o);
        if (lane == 0) rsum[wid][h] = v;
    }
    __syncthreads();
    if (t < HH){
        int idx = (b*HH + t)*K1TILES + blockIdx.x;
        g_pmax[idx] = bmax[t];
        g_psum[idx] = rsum[0][t] + rsum[1][t] + rsum[2][t] + rsum[3][t];
    }
}

// ---------------- k2: tiled softmax-apply + interp + shift + sharpen ----------
// 2048 blocks x 128 threads, 1024 elems/tile. Params recomputed per thread.
#define K2B 128
#define K2TILE 1024
__global__ __launch_bounds__(K2B) void k2_weights(const float* __restrict__ prev,
                                                  const float* __restrict__ ctrl){
    int blk  = blockIdx.x;
    int bh   = blk >> 3;
    int tilei= blk & 7;
    int t0   = tilei * K2TILE;
    int b    = bh >> 2, h = bh & 3;
    __shared__ float wi[K2TILE + 2];
    __shared__ float sMS[2];
    __shared__ float red[K2B/32];
    int t = threadIdx.x;

    // uniform param recompute (broadcast loads, ~30 flops)
    const float* c = ctrl + b*CTRL;
    float gate  = sigmoidf(c[772 + h]);
    float gamma = 1.f + softplusf(c[788 + h]);
    float a0 = c[776 + h*3 + 0], a1 = c[776 + h*3 + 1], a2 = c[776 + h*3 + 2];
    float mx = fmaxf(a0, fmaxf(a1, a2));
    float e0 = __expf(a0 - mx), e1 = __expf(a1 - mx), e2 = __expf(a2 - mx);
    float inv3 = 1.f/(e0 + e1 + e2);
    float s0 = e0*inv3, s1 = e1*inv3, s2 = e2*inv3;

    if (t < 32){
        float pm0 = g_pmax[bh*K1TILES + t];
        float pm1 = g_pmax[bh*K1TILES + t + 32];
        float ps0 = g_psum[bh*K1TILES + t];
        float ps1 = g_psum[bh*K1TILES + t + 32];
        float m = fmaxf(pm0, pm1);
        #pragma unroll
        for (int o = 16; o; o >>= 1) m = fmaxf(m, __shfl_xor_sync(0xffffffffu, m, o));
        float ss = ps0*__expf(pm0 - m) + ps1*__expf(pm1 - m);
        #pragma unroll
        for (int o = 16; o; o >>= 1) ss += __shfl_xor_sync(0xffffffffu, ss, o);
        if (t == 0){ sMS[0] = m; sMS[1] = 1.f/ss; }
    }

    const float* sc = g_scores + (size_t)bh*NN;
    const float* pr = prev     + (size_t)bh*NN;
    __syncthreads();
    float M = sMS[0], invS = sMS[1];

    float4 v0 = ((const float4*)(sc + t0))[t*2];
    float4 v1 = ((const float4*)(sc + t0))[t*2 + 1];
    float4 p0 = ((const float4*)(pr + t0))[t*2];
    float4 p1 = ((const float4*)(pr + t0))[t*2 + 1];
    float v[8]  = {v0.x, v0.y, v0.z, v0.w, v1.x, v1.y, v1.z, v1.w};
    float pv[8] = {p0.x, p0.y, p0.z, p0.w, p1.x, p1.y, p1.z, p1.w};
    #pragma unroll
    for (int j = 0; j < 8; j++)
        wi[1 + t*8 + j] = gate * (__expf(v[j] - M) * invS) + (1.f - gate) * pv[j];
    if (t == 0){
        int n = (t0 + NN - 1) & (NN - 1);
        wi[0] = gate * (__expf(sc[n] - M) * invS) + (1.f - gate) * pr[n];
    }
    if (t == 1){
        int n = (t0 + K2TILE) & (NN - 1);
        wi[K2TILE + 1] = gate * (__expf(sc[n] - M) * invS) + (1.f - gate) * pr[n];
    }
    __syncthreads();

    float pw[8];
    float ls = 0.f;
    #pragma unroll
    for (int j = 0; j < 8; j++){
        int l = t*8 + j;
        float x = s0*wi[l] + s1*wi[l + 1] + s2*wi[l + 2];
        pw[j] = __powf(x, gamma);
        ls += pw[j];
    }
    int lane = t & 31, wid = t >> 5;
    #pragma unroll
    for (int o = 16; o; o >>= 1) ls += __shfl_xor_sync(0xffffffffu, ls, o);
    if (lane == 0) red[wid] = ls;
    __syncthreads();
    if (t == 0){
        float a = red[0];
        #pragma unroll
        for (int k = 1; k < K2B/32; k++) a += red[k];
        g_tpart[bh*K2SPLIT + tilei] = a;
    }

    float* wout = g_w + (size_t)bh*NN + t0;
    float4 o0 = {pw[0], pw[1], pw[2], pw[3]};
    float4 o1 = {pw[4], pw[5], pw[6], pw[7]};
    ((float4*)wout)[t*2]     = o0;
    ((float4*)wout)[t*2 + 1] = o1;
}

// ---------------- k3: erase/add update, MLP=8; controls recomputed in-block ----
#define K3_ROWS 128
__global__ __launch_bounds__(256) void k3_out(const float* __restrict__ mem,
                                              const float* __restrict__ ctrl,
                                              float* __restrict__ out){
    int b  = blockIdx.y;
    int n0 = blockIdx.x * K3_ROWS;
    __shared__ float se[HH][WW], sv[HH][WW];
    __shared__ float sa[HH][K3_ROWS];
    __shared__ float sInvT[HH];
    int t = threadIdx.x;
    const float* c = ctrl + b*CTRL;
    se[t >> 6][t & 63] = sigmoidf(c[256 + t]);   // erase vectors
    sv[t >> 6][t & 63] = tanhf  (c[512 + t]);    // write vectors
    if (t < HH){
        float T = 0.f;
        #pragma unroll
        for (int i = 0; i < K2SPLIT; i++) T += g_tpart[(b*HH + t)*K2SPLIT + i];
        sInvT[t] = 1.f/(T + 1e-8f);
    }
    {
        int i0 = t, i1 = t + 256;
        sa[i0 >> 7][i0 & 127] = g_w[((size_t)b*HH + (i0 >> 7))*NN + n0 + (i0 & 127)];
        sa[i1 >> 7][i1 & 127] = g_w[((size_t)b*HH + (i1 >> 7))*NN + n0 + (i1 & 127)];
    }
    __syncthreads();

    int lane = t & 15, r = t >> 4;
    float4 e0 = ((const float4*)se[0])[lane];
    float4 e1 = ((const float4*)se[1])[lane];
    float4 e2 = ((const float4*)se[2])[lane];
    float4 e3 = ((const float4*)se[3])[lane];
    float4 w0 = ((const float4*)sv[0])[lane];
    float4 w1 = ((const float4*)sv[1])[lane];
    float4 w2 = ((const float4*)sv[2])[lane];
    float4 w3 = ((const float4*)sv[3])[lane];
    float it0 = sInvT[0], it1 = sInvT[1], it2 = sInvT[2], it3 = sInvT[3];

    size_t base = ((size_t)b*NN + n0 + r)*16 + lane;

    float4 m[8];
    #pragma unroll
    for (int i = 0; i < 8; i++)
        m[i] = __ldcs((const float4*)mem + base + (size_t)16*16*i);

    #pragma unroll
    for (int i = 0; i < 8; i++){
        int rr = r + 16*i;
        float a0 = sa[0][rr]*it0, a1 = sa[1][rr]*it1,
              a2 = sa[2][rr]*it2, a3 = sa[3][rr]*it3;
        float4 o;
        o.x = m[i].x*(1.f-a0*e0.x)*(1.f-a1*e1.x)*(1.f-a2*e2.x)*(1.f-a3*e3.x)
            + a0*w0.x + a1*w1.x + a2*w2.x + a3*w3.x;
        o.y = m[i].y*(1.f-a0*e0.y)*(1.f-a1*e1.y)*(1.f-a2*e2.y)*(1.f-a3*e3.y)
            + a0*w0.y + a1*w1.y + a2*w2.y + a3*w3.y;
        o.z = m[i].z*(1.f-a0*e0.z)*(1.f-a1*e1.z)*(1.f-a2*e2.z)*(1.f-a3*e3.z)
            + a0*w0.z + a1*w1.z + a2*w2.z + a3*w3.z;
        o.w = m[i].w*(1.f-a0*e0.w)*(1.f-a1*e1.w)*(1.f-a2*e2.w)*(1.f-a3*e3.w)
            + a0*w0.w + a1*w1.w + a2*w2.w + a3*w3.w;
        __stcs((float4*)out + base + (size_t)16*16*i, o);
    }
}

// ---------------- launch: three full-grid kernels ----------------
extern "C" void kernel_launch(void* const* d_in, const int* in_sizes, int n_in,
                              void* d_out, int out_size) {
    const float* mem  = (const float*)d_in[0];   // [B,N,W]
    const float* ctrl = (const float*)d_in[1];   // [B,792]
    const float* prev = (const float*)d_in[2];   // [B,H,N]
    float* out = (float*)d_out;                  // [B,N,W]

    k1_scores  <<<dim3(NN/K1_ROWSPB, BB), K1T>>>(mem, ctrl);
    k2_weights <<<BB*HH*K2SPLIT, K2B>>>(prev, ctrl);
    k3_out     <<<dim3(NN/K3_ROWS, BB), 256>>>(mem, ctrl, out);
    (void)in_sizes; (void)n_in; (void)out_size;
}